// round 16
// baseline (speedup 1.0000x reference)
#include <cuda_runtime.h>
#include <cuda_bf16.h>
#include <cstdint>
#include <math.h>

// Problem constants
#define BATCH   2
#define SLEN    2048
#define DIN     2048
#define DOUT    2048
#define NHEADS  16
#define DH      128
#define ROWS    (BATCH*SLEN)   // 4096
#define QKVCOLS (3*DOUT)       // 6144
#define APACK   4096           // packed row stride: 64 chunks x [hi32|lo32]
#define NBH     (BATCH*NHEADS) // 32
#define HEADELEMS ((size_t)SLEN*DH)  // 262144 per (b,h)
#define QK_SCALE 0.08838834764831845f

// packed offset for logical k within a row: chunk = k>>5, lane = k&31
__device__ __forceinline__ uint32_t pk(int k) { return ((uint32_t)(k >> 5) << 6) + (k & 31); }

// ---------------------------------------------------------------------------
// Scratch
// ---------------------------------------------------------------------------
__device__ float         g_v[(size_t)ROWS * DOUT];        // fp32 V (compact)
__device__ __nv_bfloat16 g_x2[(size_t)ROWS * APACK];      // x packed interleaved
__device__ __nv_bfloat16 g_wq2[(size_t)QKVCOLS * APACK];  // Wqkv^T packed
__device__ __nv_bfloat16 g_wp2[(size_t)DOUT * APACK];     // Wproj^T packed
__device__ __nv_bfloat16 g_a2[(size_t)ROWS * APACK];      // attn out packed
__device__ __nv_bfloat16 g_qh[(size_t)NBH * HEADELEMS];
__device__ __nv_bfloat16 g_ql[(size_t)NBH * HEADELEMS];
__device__ __nv_bfloat16 g_kh[(size_t)NBH * HEADELEMS];
__device__ __nv_bfloat16 g_kl[(size_t)NBH * HEADELEMS];
__device__ __nv_bfloat16 g_vth[(size_t)NBH * HEADELEMS];
__device__ __nv_bfloat16 g_vtl[(size_t)NBH * HEADELEMS];

// ---------------------------------------------------------------------------
// Helpers
// ---------------------------------------------------------------------------
__device__ __forceinline__ uint32_t smem_to_u32(const void* p) {
    uint32_t a;
    asm("{ .reg .u64 t; cvta.to.shared.u64 t, %1; cvt.u32.u64 %0, t; }" : "=r"(a) : "l"(p));
    return a;
}
__device__ __forceinline__ void split_bf16(float a, __nv_bfloat16& h, __nv_bfloat16& l) {
    h = __float2bfloat16(a);
    l = __float2bfloat16(a - __bfloat162float(h));
}
__device__ __forceinline__ void split_pack(float a, float b, uint32_t& hi, uint32_t& lo) {
    __nv_bfloat16 ha, la, hb, lb;
    split_bf16(a, ha, la);
    split_bf16(b, hb, lb);
    __nv_bfloat162 vh = __halves2bfloat162(ha, hb);
    __nv_bfloat162 vl = __halves2bfloat162(la, lb);
    hi = *reinterpret_cast<uint32_t*>(&vh);
    lo = *reinterpret_cast<uint32_t*>(&vl);
}
__device__ __forceinline__ void ldsm4(uint32_t& r0, uint32_t& r1, uint32_t& r2, uint32_t& r3,
                                      uint32_t addr) {
    asm volatile("ldmatrix.sync.aligned.m8n8.x4.shared.b16 {%0,%1,%2,%3}, [%4];"
                 : "=r"(r0), "=r"(r1), "=r"(r2), "=r"(r3) : "r"(addr));
}
__device__ __forceinline__ void mma16816(float* c,
                                         uint32_t a0, uint32_t a1, uint32_t a2, uint32_t a3,
                                         uint32_t b0, uint32_t b1) {
    asm volatile("mma.sync.aligned.m16n8k16.row.col.f32.bf16.bf16.f32 "
                 "{%0,%1,%2,%3}, {%4,%5,%6,%7}, {%8,%9}, {%0,%1,%2,%3};"
                 : "+f"(c[0]), "+f"(c[1]), "+f"(c[2]), "+f"(c[3])
                 : "r"(a0), "r"(a1), "r"(a2), "r"(a3), "r"(b0), "r"(b1));
}
__device__ __forceinline__ void cpa16(uint32_t dst, const void* src) {
    asm volatile("cp.async.cg.shared.global [%0], [%1], 16;" :: "r"(dst), "l"(src));
}
#define CP_COMMIT() asm volatile("cp.async.commit_group;" ::: "memory")
#define CP_WAIT1()  asm volatile("cp.async.wait_group 1;" ::: "memory")

// Load nrows x 128B into swizzled smem with 256 threads
__device__ __forceinline__ void load_rows(uint32_t sdst, const __nv_bfloat16* src,
                                          int srcStride, int nrows, int tid) {
    for (int i = tid; i < nrows * 8; i += 256) {
        int row = i >> 3, c = i & 7;
        uint32_t sw = (uint32_t)row * 128 + ((c * 16) ^ ((row & 7) * 16));
        cpa16(sdst + sw, src + (size_t)row * srcStride + c * 8);
    }
}

// ---------------------------------------------------------------------------
// Pack kernels: fp32 -> interleaved [hi32|lo32] per 64-elem chunk
// ---------------------------------------------------------------------------
__global__ __launch_bounds__(256) void k_split_pack(const float* __restrict__ in,
                                                    __nv_bfloat16* __restrict__ out) {
    size_t i = (size_t)blockIdx.x * blockDim.x + threadIdx.x;  // ROWS*512 float4s
    int r  = (int)(i >> 9);
    int k0 = (int)(i & 511) * 4;
    float4 v = reinterpret_cast<const float4*>(in)[i];
    __nv_bfloat16 h0,h1,h2,h3,l0,l1,l2,l3;
    split_bf16(v.x,h0,l0); split_bf16(v.y,h1,l1);
    split_bf16(v.z,h2,l2); split_bf16(v.w,h3,l3);
    __nv_bfloat16* o = out + (size_t)r * APACK + pk(k0);
    __nv_bfloat162* oh = reinterpret_cast<__nv_bfloat162*>(o);
    __nv_bfloat162* ol = reinterpret_cast<__nv_bfloat162*>(o + 32);
    oh[0] = __halves2bfloat162(h0,h1); oh[1] = __halves2bfloat162(h2,h3);
    ol[0] = __halves2bfloat162(l0,l1); ol[1] = __halves2bfloat162(l2,l3);
}

__global__ __launch_bounds__(256) void k_tsplit_pack(const float* __restrict__ in,
                                                     __nv_bfloat16* __restrict__ out,
                                                     int C) {
    __shared__ float t[32][33];
    int c0 = blockIdx.x * 32, r0 = blockIdx.y * 32;
    int tx = threadIdx.x, ty = threadIdx.y;
#pragma unroll
    for (int i = 0; i < 32; i += 8)
        t[ty + i][tx] = in[(size_t)(r0 + ty + i) * C + c0 + tx];
    __syncthreads();
#pragma unroll
    for (int i = 0; i < 32; i += 8) {
        float a = t[tx][ty + i];
        __nv_bfloat16 h, l;
        split_bf16(a, h, l);
        size_t n = (size_t)(c0 + ty + i);
        int    k = r0 + tx;
        __nv_bfloat16* o = out + n * APACK + pk(k);
        o[0]  = h;
        o[32] = l;
    }
}

// V transpose+split: g_v -> g_vth/g_vtl [bh][d][s]
__global__ __launch_bounds__(256) void k_prep_vt() {   // grid (4, 64, 32), block (32,8)
    __shared__ float t[32][33];
    int d0 = blockIdx.x * 32, s0 = blockIdx.y * 32, bh = blockIdx.z;
    int b = bh >> 4, h = bh & 15;
    int tx = threadIdx.x, ty = threadIdx.y;
#pragma unroll
    for (int i = 0; i < 32; i += 8)
        t[ty + i][tx] = g_v[(size_t)(b*2048 + s0 + ty + i)*DOUT + h*128 + d0 + tx];
    __syncthreads();
#pragma unroll
    for (int i = 0; i < 32; i += 8) {
        float a = t[tx][ty + i];
        __nv_bfloat16 hh, ll;
        split_bf16(a, hh, ll);
        size_t o = (size_t)bh * HEADELEMS + (size_t)(d0 + ty + i)*2048 + s0 + tx;
        g_vth[o] = hh;
        g_vtl[o] = ll;
    }
}

// ---------------------------------------------------------------------------
// bf16x3 GEMM v8: v7 + load hoisting (Al joins Ah/Bh at k-step top; k-step-0
// loads hoisted above cp.async issue). MMA term order unchanged (AhBh, AlBh,
// AhBl) -> bit-identical results to v7. Peak live fragments unchanged (40).
// ---------------------------------------------------------------------------
#define NKIT  64                // 4096 / 64B-chunk
#define STG   32768
#define GEMM_SMEM (1024 + 3 * STG)

__device__ __forceinline__ void load_tile_pair(uint32_t sA, uint32_t sB,
                                               const __nv_bfloat16* gA,
                                               const __nv_bfloat16* gB, int tid) {
#pragma unroll
    for (int t = 0; t < 4; ++t) {
        int i = tid + t * 256;
        int row = i >> 3, c = i & 7;
        uint32_t sw = (uint32_t)row * 128 + ((c * 16) ^ ((row & 7) * 16));
        cpa16(sA + sw, gA + (size_t)row * APACK + c * 8);
        cpa16(sB + sw, gB + (size_t)row * APACK + c * 8);
    }
}

template <int MODE>
__global__ __launch_bounds__(256, 2) void k_gemm_v8(const __nv_bfloat16* __restrict__ A,
                                                    const __nv_bfloat16* __restrict__ B,
                                                    const float* __restrict__ bias,
                                                    float* __restrict__ C, int N) {
    extern __shared__ char smraw[];
    uint32_t sbase = (smem_to_u32(smraw) + 1023) & ~1023u;
    const int tid = threadIdx.x;
    const int m0 = blockIdx.y * 128, n0 = blockIdx.x * 128;
    const __nv_bfloat16* Ab = A + (size_t)m0 * APACK;
    const __nv_bfloat16* Bb = B + (size_t)n0 * APACK;

    load_tile_pair(sbase,       sbase + 16384,       Ab,      Bb,      tid);
    CP_COMMIT();
    load_tile_pair(sbase + STG, sbase + STG + 16384, Ab + 64, Bb + 64, tid);
    CP_COMMIT();

    float c[4][4][4];
#pragma unroll
    for (int i = 0; i < 4; i++)
#pragma unroll
        for (int j = 0; j < 4; j++)
#pragma unroll
            for (int q = 0; q < 4; q++) c[i][j][q] = 0.f;

    const int wid = tid >> 5, lane = tid & 31;
    const int wm = wid & 1, wn = wid >> 1;
    const int a_row_base = wm * 64 + ((lane >> 3) & 1) * 8 + (lane & 7);
    const int a_byte     = (lane >> 4) * 16;
    const int b_row_off  = ((lane >> 4) & 1) * 8 + (lane & 7);
    const int b_byte     = ((lane >> 3) & 1) * 16;

    uint32_t Ah[4][4], Al[4][4], Bh[2][4], Bl[2][4];

    // load Ah/Bh/Al fragments for k16-step s (hi at s*32, lo at 64+s*32)
#define LOAD_HDR(bufA, bufB, s) do { \
        const int _hb = (s) * 32, _lb = 64 + (s) * 32; \
        _Pragma("unroll") \
        for (int am = 0; am < 4; ++am) { \
            int row = a_row_base + am * 16; \
            uint32_t off = (uint32_t)row * 128 + ((_hb + a_byte) ^ ((row & 7) * 16)); \
            ldsm4(Ah[am][0], Ah[am][1], Ah[am][2], Ah[am][3], (bufA) + off); \
        } \
        _Pragma("unroll") \
        for (int p = 0; p < 2; ++p) { \
            int row = wn * 32 + p * 16 + b_row_off; \
            uint32_t off = (uint32_t)row * 128 + ((_hb + b_byte) ^ ((row & 7) * 16)); \
            ldsm4(Bh[p][0], Bh[p][1], Bh[p][2], Bh[p][3], (bufB) + off); \
        } \
        _Pragma("unroll") \
        for (int am = 0; am < 4; ++am) { \
            int row = a_row_base + am * 16; \
            uint32_t off = (uint32_t)row * 128 + ((_lb + a_byte) ^ ((row & 7) * 16)); \
            ldsm4(Al[am][0], Al[am][1], Al[am][2], Al[am][3], (bufA) + off); \
        } \
    } while (0)

    int stc = 0, stn = 2;
    for (int kt = 0; kt < NKIT; ++kt) {
        CP_WAIT1();
        __syncthreads();

        uint32_t bufA = sbase + stc * STG;
        uint32_t bufB = bufA + 16384;

        LOAD_HDR(bufA, bufB, 0);     // s=0 loads hidden behind cp.async issue

        if (kt + 2 < NKIT) {
            uint32_t nb = sbase + stn * STG;
            load_tile_pair(nb, nb + 16384, Ab + (kt + 2) * 64, Bb + (kt + 2) * 64, tid);
        }
        CP_COMMIT();

#pragma unroll
        for (int s = 0; s < 2; ++s) {
            if (s == 1) LOAD_HDR(bufA, bufB, 1);
            const int lb = 64 + s * 32;
            // AhBh
#pragma unroll
            for (int am = 0; am < 4; ++am)
#pragma unroll
                for (int an = 0; an < 4; ++an)
                    mma16816(c[am][an], Ah[am][0], Ah[am][1], Ah[am][2], Ah[am][3],
                             Bh[an >> 1][(an & 1) * 2], Bh[an >> 1][(an & 1) * 2 + 1]);
            // AlBh
#pragma unroll
            for (int am = 0; am < 4; ++am)
#pragma unroll
                for (int an = 0; an < 4; ++an)
                    mma16816(c[am][an], Al[am][0], Al[am][1], Al[am][2], Al[am][3],
                             Bh[an >> 1][(an & 1) * 2], Bh[an >> 1][(an & 1) * 2 + 1]);
            // Bl load (Al/Bh registers now dead for this k-step)
#pragma unroll
            for (int p = 0; p < 2; ++p) {
                int row = wn * 32 + p * 16 + b_row_off;
                uint32_t off = (uint32_t)row * 128 + ((lb + b_byte) ^ ((row & 7) * 16));
                ldsm4(Bl[p][0], Bl[p][1], Bl[p][2], Bl[p][3], bufB + off);
            }
            // AhBl
#pragma unroll
            for (int am = 0; am < 4; ++am)
#pragma unroll
                for (int an = 0; an < 4; ++an)
                    mma16816(c[am][an], Ah[am][0], Ah[am][1], Ah[am][2], Ah[am][3],
                             Bl[an >> 1][(an & 1) * 2], Bl[an >> 1][(an & 1) * 2 + 1]);
        }
        stc = (stc == 2) ? 0 : stc + 1;
        stn = (stn == 2) ? 0 : stn + 1;
    }
#undef LOAD_HDR

    // ---- Epilogue ----
    if (MODE == 1) {
#pragma unroll
        for (int am = 0; am < 4; ++am) {
            int r = m0 + wm * 64 + am * 16 + (lane >> 2);
#pragma unroll
            for (int an = 0; an < 4; ++an) {
                int col = n0 + wn * 32 + an * 8 + (lane & 3) * 2;
                float b0 = bias[col], b1 = bias[col + 1];
                float2 v0 = make_float2(c[am][an][0] + b0, c[am][an][1] + b1);
                float2 v1 = make_float2(c[am][an][2] + b0, c[am][an][3] + b1);
                *reinterpret_cast<float2*>(C + (size_t)r * N + col)       = v0;
                *reinterpret_cast<float2*>(C + (size_t)(r + 8) * N + col) = v1;
            }
        }
    } else {
        const int part = n0 >> 11;   // 0=q, 1=k, 2=v
#pragma unroll
        for (int am = 0; am < 4; ++am) {
            int r = m0 + wm * 64 + am * 16 + (lane >> 2);
            int b = r >> 11, s = r & 2047;
#pragma unroll
            for (int an = 0; an < 4; ++an) {
                int n = n0 + wn * 32 + an * 8 + (lane & 3) * 2;
                int h = (n & 2047) >> 7, d = n & 127;
                float v0 = c[am][an][0], v1 = c[am][an][1];
                float v2 = c[am][an][2], v3 = c[am][an][3];
                if (part == 2) {
                    size_t o = (size_t)(b * 2048 + s) * DOUT + h * 128 + d;
                    *reinterpret_cast<float2*>(g_v + o)            = make_float2(v0, v1);
                    *reinterpret_cast<float2*>(g_v + o + 8 * DOUT) = make_float2(v2, v3);
                } else {
                    __nv_bfloat16* dh = (part == 0) ? g_qh : g_kh;
                    __nv_bfloat16* dl = (part == 0) ? g_ql : g_kl;
                    float sc = (part == 0) ? QK_SCALE : 1.0f;
                    size_t o = (size_t)(b * 16 + h) * HEADELEMS + (size_t)s * 128 + d;
                    uint32_t hi, lo;
                    split_pack(v0 * sc, v1 * sc, hi, lo);
                    *reinterpret_cast<uint32_t*>(dh + o) = hi;
                    *reinterpret_cast<uint32_t*>(dl + o) = lo;
                    split_pack(v2 * sc, v3 * sc, hi, lo);
                    *reinterpret_cast<uint32_t*>(dh + o + 8 * 128) = hi;
                    *reinterpret_cast<uint32_t*>(dl + o + 8 * 128) = lo;
                }
            }
        }
    }
}

// ---------------------------------------------------------------------------
// Tensor-core flash attention (bf16x3), causal. Round-15 proven (LPT grid +
// last-tile warp skip + Q hoist). Epilogue writes interleaved-packed g_a2.
// ---------------------------------------------------------------------------
#define ATT_SMEM (1024 + 196608)

__global__ __launch_bounds__(256) void k_attn_tc() {
    extern __shared__ char smraw[];
    uint32_t sb = (smem_to_u32(smraw) + 1023) & ~1023u;
    const int tid = threadIdx.x, w = tid >> 5, lane = tid & 31;
    const int qblk = 15 - blockIdx.y;      // global heavy-first (LPT)
    const int bh   = blockIdx.x;
    const int q0   = qblk * 128;
    const size_t hb = (size_t)bh * HEADELEMS;

    const __nv_bfloat16* Qh  = g_qh  + hb + (size_t)q0 * 128;
    const __nv_bfloat16* Ql  = g_ql  + hb + (size_t)q0 * 128;
    const __nv_bfloat16* Kh  = g_kh  + hb;
    const __nv_bfloat16* Kl  = g_kl  + hb;
    const __nv_bfloat16* Vth = g_vth + hb;
    const __nv_bfloat16* Vtl = g_vtl + hb;

    load_rows(sb + 0,     Qh,      128, 128, tid);
    load_rows(sb + 16384, Qh + 64, 128, 128, tid);
    load_rows(sb + 32768, Ql,      128, 128, tid);
    load_rows(sb + 49152, Ql + 64, 128, 128, tid);
    {
        uint32_t kb = sb + 65536, vb = sb + 131072;
        load_rows(kb + 0,     Kh,      128, 64, tid);
        load_rows(kb + 8192,  Kh + 64, 128, 64, tid);
        load_rows(kb + 16384, Kl,      128, 64, tid);
        load_rows(kb + 24576, Kl + 64, 128, 64, tid);
        load_rows(vb + 0,     Vth,     2048, 128, tid);
        load_rows(vb + 16384, Vtl,     2048, 128, tid);
    }
    CP_COMMIT();

    const int ntiles = 2 * qblk + 2;

    float oc[16][4];
#pragma unroll
    for (int i = 0; i < 16; i++)
#pragma unroll
        for (int q = 0; q < 4; q++) oc[i][q] = 0.f;
    float m0 = -1e30f, m1 = -1e30f, l0 = 0.f, l1 = 0.f;

    const int a_row  = w * 16 + ((lane >> 3) & 1) * 8 + (lane & 7);
    const int a_byte = (lane >> 4) * 16;
    const int b_row  = ((lane >> 4) & 1) * 8 + (lane & 7);
    const int b_byte = ((lane >> 3) & 1) * 16;

    uint32_t qfh[8][4], qfl[8][4];

    for (int j = 0; j < ntiles; ++j) {
        if (j + 1 < ntiles) {
            uint32_t kb = sb + 65536  + ((j + 1) & 1) * 32768;
            uint32_t vb = sb + 131072 + ((j + 1) & 1) * 32768;
            const __nv_bfloat16* kh = Kh + (size_t)(j + 1) * 64 * 128;
            const __nv_bfloat16* kl = Kl + (size_t)(j + 1) * 64 * 128;
            load_rows(kb + 0,     kh,      128, 64, tid);
            load_rows(kb + 8192,  kh + 64, 128, 64, tid);
            load_rows(kb + 16384, kl,      128, 64, tid);
            load_rows(kb + 24576, kl + 64, 128, 64, tid);
            load_rows(vb + 0,     Vth + (j + 1) * 64, 2048, 128, tid);
            load_rows(vb + 16384, Vtl + (j + 1) * 64, 2048, 128, tid);
        }
        CP_COMMIT();
        CP_WAIT1();
        __syncthreads();

        if (j == 0) {
#pragma unroll
            for (int kst = 0; kst < 8; ++kst) {
                int ch = kst >> 2, sby = (kst & 3) * 32;
                uint32_t qoff = (uint32_t)a_row * 128 + ((sby + a_byte) ^ ((a_row & 7) * 16));
                ldsm4(qfh[kst][0], qfh[kst][1], qfh[kst][2], qfh[kst][3], sb + ch * 16384 + qoff);
                ldsm4(qfl[kst][0], qfl[kst][1], qfl[kst][2], qfl[kst][3], sb + 32768 + ch * 16384 + qoff);
            }
        }

        if (!(j == ntiles - 1 && w < 4)) {

        uint32_t kb = sb + 65536  + (j & 1) * 32768;
        uint32_t vb = sb + 131072 + (j & 1) * 32768;

        float sc[8][4];
#pragma unroll
        for (int t = 0; t < 8; t++)
#pragma unroll
            for (int q = 0; q < 4; q++) sc[t][q] = 0.f;

#pragma unroll
        for (int kst = 0; kst < 8; ++kst) {
            int ch = kst >> 2, sby = (kst & 3) * 32;
            uint32_t bhf[4][4], blf[4][4];
#pragma unroll
            for (int p = 0; p < 4; ++p) {
                int row = p * 16 + b_row;
                uint32_t off = (uint32_t)row * 128 + ((sby + b_byte) ^ ((row & 7) * 16));
                ldsm4(bhf[p][0], bhf[p][1], bhf[p][2], bhf[p][3], kb + ch * 8192 + off);
                ldsm4(blf[p][0], blf[p][1], blf[p][2], blf[p][3], kb + 16384 + ch * 8192 + off);
            }
#pragma unroll
            for (int t = 0; t < 8; ++t) {
                int p = t >> 1, rr = (t & 1) * 2;
                mma16816(sc[t], qfh[kst][0], qfh[kst][1], qfh[kst][2], qfh[kst][3],
                         bhf[p][rr], bhf[p][rr + 1]);
                mma16816(sc[t], qfh[kst][0], qfh[kst][1], qfh[kst][2], qfh[kst][3],
                         blf[p][rr], blf[p][rr + 1]);
                mma16816(sc[t], qfl[kst][0], qfl[kst][1], qfl[kst][2], qfl[kst][3],
                         bhf[p][rr], bhf[p][rr + 1]);
            }
        }

        if (j >= 2 * qblk) {
            int kbase = j * 64 + (lane & 3) * 2;
            int qrow  = q0 + w * 16 + (lane >> 2);
#pragma unroll
            for (int t = 0; t < 8; ++t) {
                int kc = kbase + t * 8;
                if (kc     > qrow)     sc[t][0] = -1e30f;
                if (kc + 1 > qrow)     sc[t][1] = -1e30f;
                if (kc     > qrow + 8) sc[t][2] = -1e30f;
                if (kc + 1 > qrow + 8) sc[t][3] = -1e30f;
            }
        }

        uint32_t pha0[8], pha1[8], pla0[8], pla1[8];
        float alpha0, alpha1;
        {
            float mx = -1e30f;
#pragma unroll
            for (int t = 0; t < 8; ++t) mx = fmaxf(mx, fmaxf(sc[t][0], sc[t][1]));
            mx = fmaxf(mx, __shfl_xor_sync(0xffffffffu, mx, 1));
            mx = fmaxf(mx, __shfl_xor_sync(0xffffffffu, mx, 2));
            float mn = fmaxf(m0, mx);
            alpha0 = __expf(m0 - mn); m0 = mn;
            float sum = 0.f;
#pragma unroll
            for (int t = 0; t < 8; ++t) {
                float p0 = __expf(sc[t][0] - mn), p1 = __expf(sc[t][1] - mn);
                sum += p0 + p1;
                split_pack(p0, p1, pha0[t], pla0[t]);
            }
            sum += __shfl_xor_sync(0xffffffffu, sum, 1);
            sum += __shfl_xor_sync(0xffffffffu, sum, 2);
            l0 = l0 * alpha0 + sum;
        }
        {
            float mx = -1e30f;
#pragma unroll
            for (int t = 0; t < 8; ++t) mx = fmaxf(mx, fmaxf(sc[t][2], sc[t][3]));
            mx = fmaxf(mx, __shfl_xor_sync(0xffffffffu, mx, 1));
            mx = fmaxf(mx, __shfl_xor_sync(0xffffffffu, mx, 2));
            float mn = fmaxf(m1, mx);
            alpha1 = __expf(m1 - mn); m1 = mn;
            float sum = 0.f;
#pragma unroll
            for (int t = 0; t < 8; ++t) {
                float p0 = __expf(sc[t][2] - mn), p1 = __expf(sc[t][3] - mn);
                sum += p0 + p1;
                split_pack(p0, p1, pha1[t], pla1[t]);
            }
            sum += __shfl_xor_sync(0xffffffffu, sum, 1);
            sum += __shfl_xor_sync(0xffffffffu, sum, 2);
            l1 = l1 * alpha1 + sum;
        }
#pragma unroll
        for (int dt = 0; dt < 16; ++dt) {
            oc[dt][0] *= alpha0; oc[dt][1] *= alpha0;
            oc[dt][2] *= alpha1; oc[dt][3] *= alpha1;
        }

#pragma unroll
        for (int kk = 0; kk < 4; ++kk) {
            uint32_t Ah0 = pha0[2*kk],   Ah1 = pha1[2*kk];
            uint32_t Ah2 = pha0[2*kk+1], Ah3 = pha1[2*kk+1];
            uint32_t Al0 = pla0[2*kk],   Al1 = pla1[2*kk];
            uint32_t Al2 = pla0[2*kk+1], Al3 = pla1[2*kk+1];
            uint32_t bhf[8][4], blf[8][4];
#pragma unroll
            for (int p = 0; p < 8; ++p) {
                int row = p * 16 + b_row;
                uint32_t off = (uint32_t)row * 128 + ((kk * 32 + b_byte) ^ ((row & 7) * 16));
                ldsm4(bhf[p][0], bhf[p][1], bhf[p][2], bhf[p][3], vb + off);
                ldsm4(blf[p][0], blf[p][1], blf[p][2], blf[p][3], vb + 16384 + off);
            }
#pragma unroll
            for (int dt = 0; dt < 16; ++dt) {
                int p = dt >> 1, rr = (dt & 1) * 2;
                mma16816(oc[dt], Ah0, Ah1, Ah2, Ah3, bhf[p][rr], bhf[p][rr + 1]);
                mma16816(oc[dt], Ah0, Ah1, Ah2, Ah3, blf[p][rr], blf[p][rr + 1]);
                mma16816(oc[dt], Al0, Al1, Al2, Al3, bhf[p][rr], bhf[p][rr + 1]);
            }
        }

        }   // end skip guard
        __syncthreads();
    }

    // ---- epilogue: O / l -> g_a2 interleaved packed [hi32|lo32] ----
    float inv0 = 1.f / l0, inv1 = 1.f / l1;
    int b = bh >> 4, h = bh & 15;
    int r0 = q0 + w * 16 + (lane >> 2);
    size_t base0 = (size_t)(b * 2048 + r0) * APACK;
    size_t base1 = base0 + (size_t)8 * APACK;
#pragma unroll
    for (int dt = 0; dt < 16; ++dt) {
        int d = dt * 8 + (lane & 3) * 2;
        uint32_t off = pk(h * 128 + d);
        uint32_t hi, lo;
        split_pack(oc[dt][0] * inv0, oc[dt][1] * inv0, hi, lo);
        *reinterpret_cast<uint32_t*>(g_a2 + base0 + off)      = hi;
        *reinterpret_cast<uint32_t*>(g_a2 + base0 + off + 32) = lo;
        split_pack(oc[dt][2] * inv1, oc[dt][3] * inv1, hi, lo);
        *reinterpret_cast<uint32_t*>(g_a2 + base1 + off)      = hi;
        *reinterpret_cast<uint32_t*>(g_a2 + base1 + off + 32) = lo;
    }
}

// ---------------------------------------------------------------------------
// Launch
// ---------------------------------------------------------------------------
extern "C" void kernel_launch(void* const* d_in, const int* in_sizes, int n_in,
                              void* d_out, int out_size) {
    const float* x     = (const float*)d_in[0];
    const float* Wqkv  = (const float*)d_in[1];
    const float* Wproj = (const float*)d_in[2];
    const float* bproj = (const float*)d_in[3];
    float* out = (float*)d_out;
    (void)in_sizes; (void)n_in; (void)out_size;

    cudaFuncSetAttribute(k_gemm_v8<0>, cudaFuncAttributeMaxDynamicSharedMemorySize, GEMM_SMEM);
    cudaFuncSetAttribute(k_gemm_v8<1>, cudaFuncAttributeMaxDynamicSharedMemorySize, GEMM_SMEM);
    cudaFuncSetAttribute(k_attn_tc,    cudaFuncAttributeMaxDynamicSharedMemorySize, ATT_SMEM);

    __nv_bfloat16 *x2, *wq2, *wp2, *a2;
    cudaGetSymbolAddress((void**)&x2,  g_x2);
    cudaGetSymbolAddress((void**)&wq2, g_wq2);
    cudaGetSymbolAddress((void**)&wp2, g_wp2);
    cudaGetSymbolAddress((void**)&a2,  g_a2);

    // 1) Pack inputs (interleaved hi|lo)
    k_split_pack<<<(ROWS * 2048 / 4) / 256, 256>>>(x, x2);
    k_tsplit_pack<<<dim3(QKVCOLS / 32, 2048 / 32), dim3(32, 8)>>>(Wqkv, wq2, QKVCOLS);
    k_tsplit_pack<<<dim3(DOUT / 32, 2048 / 32), dim3(32, 8)>>>(Wproj, wp2, DOUT);

    // 2) GEMM1 fused: q/k hi-lo splits (scaled) + fp32 V
    k_gemm_v8<0><<<dim3(QKVCOLS / 128, ROWS / 128), 256, GEMM_SMEM>>>(
        x2, wq2, nullptr, nullptr, QKVCOLS);

    // 3) V transpose+split
    k_prep_vt<<<dim3(4, 64, 32), dim3(32, 8)>>>();

    // 4) Tensor-core attention -> g_a2 (LPT grid)
    k_attn_tc<<<dim3(32, 16), 256, ATT_SMEM>>>();

    // 5) GEMM2: out = attn @ Wproj + bias
    k_gemm_v8<1><<<dim3(DOUT / 128, ROWS / 128), 256, GEMM_SMEM>>>(
        a2, wp2, bproj, out, DOUT);
}

// round 17
// speedup vs baseline: 1.0256x; 1.0256x over previous
#include <cuda_runtime.h>
#include <cuda_bf16.h>
#include <cstdint>
#include <math.h>

// Problem constants
#define BATCH   2
#define SLEN    2048
#define DIN     2048
#define DOUT    2048
#define NHEADS  16
#define DH      128
#define ROWS    (BATCH*SLEN)   // 4096
#define QKVCOLS (3*DOUT)       // 6144
#define APACK   4096           // packed row stride: 64 chunks x [hi32|lo32]
#define NBH     (BATCH*NHEADS) // 32
#define HEADELEMS ((size_t)SLEN*DH)  // 262144 per (b,h)
#define QK_SCALE 0.08838834764831845f

// packed offset for logical k within a row: chunk = k>>5, lane = k&31
__device__ __forceinline__ uint32_t pk(int k) { return ((uint32_t)(k >> 5) << 6) + (k & 31); }

// ---------------------------------------------------------------------------
// Scratch
// ---------------------------------------------------------------------------
__device__ float         g_v[(size_t)ROWS * DOUT];        // fp32 V (compact)
__device__ __nv_bfloat16 g_x2[(size_t)ROWS * APACK];      // x packed interleaved
__device__ __nv_bfloat16 g_wq2[(size_t)QKVCOLS * APACK];  // Wqkv^T packed
__device__ __nv_bfloat16 g_wp2[(size_t)DOUT * APACK];     // Wproj^T packed
__device__ __nv_bfloat16 g_a2[(size_t)ROWS * APACK];      // attn out packed
__device__ __nv_bfloat16 g_qh[(size_t)NBH * HEADELEMS];
__device__ __nv_bfloat16 g_ql[(size_t)NBH * HEADELEMS];
__device__ __nv_bfloat16 g_kh[(size_t)NBH * HEADELEMS];
__device__ __nv_bfloat16 g_kl[(size_t)NBH * HEADELEMS];
__device__ __nv_bfloat16 g_vth[(size_t)NBH * HEADELEMS];
__device__ __nv_bfloat16 g_vtl[(size_t)NBH * HEADELEMS];

// ---------------------------------------------------------------------------
// Helpers
// ---------------------------------------------------------------------------
__device__ __forceinline__ uint32_t smem_to_u32(const void* p) {
    uint32_t a;
    asm("{ .reg .u64 t; cvta.to.shared.u64 t, %1; cvt.u32.u64 %0, t; }" : "=r"(a) : "l"(p));
    return a;
}
__device__ __forceinline__ void split_bf16(float a, __nv_bfloat16& h, __nv_bfloat16& l) {
    h = __float2bfloat16(a);
    l = __float2bfloat16(a - __bfloat162float(h));
}
__device__ __forceinline__ void split_pack(float a, float b, uint32_t& hi, uint32_t& lo) {
    __nv_bfloat16 ha, la, hb, lb;
    split_bf16(a, ha, la);
    split_bf16(b, hb, lb);
    __nv_bfloat162 vh = __halves2bfloat162(ha, hb);
    __nv_bfloat162 vl = __halves2bfloat162(la, lb);
    hi = *reinterpret_cast<uint32_t*>(&vh);
    lo = *reinterpret_cast<uint32_t*>(&vl);
}
__device__ __forceinline__ void ldsm4(uint32_t& r0, uint32_t& r1, uint32_t& r2, uint32_t& r3,
                                      uint32_t addr) {
    asm volatile("ldmatrix.sync.aligned.m8n8.x4.shared.b16 {%0,%1,%2,%3}, [%4];"
                 : "=r"(r0), "=r"(r1), "=r"(r2), "=r"(r3) : "r"(addr));
}
__device__ __forceinline__ void mma16816(float* c,
                                         uint32_t a0, uint32_t a1, uint32_t a2, uint32_t a3,
                                         uint32_t b0, uint32_t b1) {
    asm volatile("mma.sync.aligned.m16n8k16.row.col.f32.bf16.bf16.f32 "
                 "{%0,%1,%2,%3}, {%4,%5,%6,%7}, {%8,%9}, {%0,%1,%2,%3};"
                 : "+f"(c[0]), "+f"(c[1]), "+f"(c[2]), "+f"(c[3])
                 : "r"(a0), "r"(a1), "r"(a2), "r"(a3), "r"(b0), "r"(b1));
}
__device__ __forceinline__ void cpa16(uint32_t dst, const void* src) {
    asm volatile("cp.async.cg.shared.global [%0], [%1], 16;" :: "r"(dst), "l"(src));
}
#define CP_COMMIT() asm volatile("cp.async.commit_group;" ::: "memory")
#define CP_WAIT1()  asm volatile("cp.async.wait_group 1;" ::: "memory")

// Load nrows x 128B into swizzled smem with 256 threads
__device__ __forceinline__ void load_rows(uint32_t sdst, const __nv_bfloat16* src,
                                          int srcStride, int nrows, int tid) {
    for (int i = tid; i < nrows * 8; i += 256) {
        int row = i >> 3, c = i & 7;
        uint32_t sw = (uint32_t)row * 128 + ((c * 16) ^ ((row & 7) * 16));
        cpa16(sdst + sw, src + (size_t)row * srcStride + c * 8);
    }
}

// ---------------------------------------------------------------------------
// Pack kernels: fp32 -> interleaved [hi32|lo32] per 64-elem chunk
// ---------------------------------------------------------------------------
__global__ __launch_bounds__(256) void k_split_pack(const float* __restrict__ in,
                                                    __nv_bfloat16* __restrict__ out) {
    size_t i = (size_t)blockIdx.x * blockDim.x + threadIdx.x;  // ROWS*512 float4s
    int r  = (int)(i >> 9);
    int k0 = (int)(i & 511) * 4;
    float4 v = reinterpret_cast<const float4*>(in)[i];
    __nv_bfloat16 h0,h1,h2,h3,l0,l1,l2,l3;
    split_bf16(v.x,h0,l0); split_bf16(v.y,h1,l1);
    split_bf16(v.z,h2,l2); split_bf16(v.w,h3,l3);
    __nv_bfloat16* o = out + (size_t)r * APACK + pk(k0);
    __nv_bfloat162* oh = reinterpret_cast<__nv_bfloat162*>(o);
    __nv_bfloat162* ol = reinterpret_cast<__nv_bfloat162*>(o + 32);
    oh[0] = __halves2bfloat162(h0,h1); oh[1] = __halves2bfloat162(h2,h3);
    ol[0] = __halves2bfloat162(l0,l1); ol[1] = __halves2bfloat162(l2,l3);
}

__global__ __launch_bounds__(256) void k_tsplit_pack(const float* __restrict__ in,
                                                     __nv_bfloat16* __restrict__ out,
                                                     int C) {
    __shared__ float t[32][33];
    int c0 = blockIdx.x * 32, r0 = blockIdx.y * 32;
    int tx = threadIdx.x, ty = threadIdx.y;
#pragma unroll
    for (int i = 0; i < 32; i += 8)
        t[ty + i][tx] = in[(size_t)(r0 + ty + i) * C + c0 + tx];
    __syncthreads();
#pragma unroll
    for (int i = 0; i < 32; i += 8) {
        float a = t[tx][ty + i];
        __nv_bfloat16 h, l;
        split_bf16(a, h, l);
        size_t n = (size_t)(c0 + ty + i);
        int    k = r0 + tx;
        __nv_bfloat16* o = out + n * APACK + pk(k);
        o[0]  = h;
        o[32] = l;
    }
}

// V transpose+split: g_v -> g_vth/g_vtl [bh][d][s]
__global__ __launch_bounds__(256) void k_prep_vt() {   // grid (4, 64, 32), block (32,8)
    __shared__ float t[32][33];
    int d0 = blockIdx.x * 32, s0 = blockIdx.y * 32, bh = blockIdx.z;
    int b = bh >> 4, h = bh & 15;
    int tx = threadIdx.x, ty = threadIdx.y;
#pragma unroll
    for (int i = 0; i < 32; i += 8)
        t[ty + i][tx] = g_v[(size_t)(b*2048 + s0 + ty + i)*DOUT + h*128 + d0 + tx];
    __syncthreads();
#pragma unroll
    for (int i = 0; i < 32; i += 8) {
        float a = t[tx][ty + i];
        __nv_bfloat16 hh, ll;
        split_bf16(a, hh, ll);
        size_t o = (size_t)bh * HEADELEMS + (size_t)(d0 + ty + i)*2048 + s0 + tx;
        g_vth[o] = hh;
        g_vtl[o] = ll;
    }
}

// ---------------------------------------------------------------------------
// bf16x3 GEMM v7 (proven round 15): interleaved hi|lo operands, register
// fragment reuse, load-just-before-use (short fragment lifetimes).
// CTA 128x128, chunk K=32 (stage 32KB), 3-stage cp.async.
// ---------------------------------------------------------------------------
#define NKIT  64                // 4096 / 64B-chunk
#define STG   32768
#define GEMM_SMEM (1024 + 3 * STG)

__device__ __forceinline__ void load_tile_pair(uint32_t sA, uint32_t sB,
                                               const __nv_bfloat16* gA,
                                               const __nv_bfloat16* gB, int tid) {
#pragma unroll
    for (int t = 0; t < 4; ++t) {
        int i = tid + t * 256;
        int row = i >> 3, c = i & 7;
        uint32_t sw = (uint32_t)row * 128 + ((c * 16) ^ ((row & 7) * 16));
        cpa16(sA + sw, gA + (size_t)row * APACK + c * 8);
        cpa16(sB + sw, gB + (size_t)row * APACK + c * 8);
    }
}

template <int MODE>
__global__ __launch_bounds__(256, 2) void k_gemm_v7(const __nv_bfloat16* __restrict__ A,
                                                    const __nv_bfloat16* __restrict__ B,
                                                    const float* __restrict__ bias,
                                                    float* __restrict__ C, int N) {
    extern __shared__ char smraw[];
    uint32_t sbase = (smem_to_u32(smraw) + 1023) & ~1023u;
    const int tid = threadIdx.x;
    const int m0 = blockIdx.y * 128, n0 = blockIdx.x * 128;
    const __nv_bfloat16* Ab = A + (size_t)m0 * APACK;
    const __nv_bfloat16* Bb = B + (size_t)n0 * APACK;

    load_tile_pair(sbase,       sbase + 16384,       Ab,      Bb,      tid);
    CP_COMMIT();
    load_tile_pair(sbase + STG, sbase + STG + 16384, Ab + 64, Bb + 64, tid);
    CP_COMMIT();

    float c[4][4][4];
#pragma unroll
    for (int i = 0; i < 4; i++)
#pragma unroll
        for (int j = 0; j < 4; j++)
#pragma unroll
            for (int q = 0; q < 4; q++) c[i][j][q] = 0.f;

    const int wid = tid >> 5, lane = tid & 31;
    const int wm = wid & 1, wn = wid >> 1;
    const int a_row_base = wm * 64 + ((lane >> 3) & 1) * 8 + (lane & 7);
    const int a_byte     = (lane >> 4) * 16;
    const int b_row_off  = ((lane >> 4) & 1) * 8 + (lane & 7);
    const int b_byte     = ((lane >> 3) & 1) * 16;

    int stc = 0, stn = 2;
    for (int kt = 0; kt < NKIT; ++kt) {
        CP_WAIT1();
        __syncthreads();
        if (kt + 2 < NKIT) {
            uint32_t nb = sbase + stn * STG;
            load_tile_pair(nb, nb + 16384, Ab + (kt + 2) * 64, Bb + (kt + 2) * 64, tid);
        }
        CP_COMMIT();

        uint32_t bufA = sbase + stc * STG;
        uint32_t bufB = bufA + 16384;
#pragma unroll
        for (int s = 0; s < 2; ++s) {       // 2 k16-steps per 32-chunk
            const int hb = s * 32;          // hi bytes [0,64)
            const int lb = 64 + s * 32;     // lo bytes [64,128)
            uint32_t Ah[4][4], Al[4][4], Bh[2][4], Bl[2][4];
            // Ah + Bh
#pragma unroll
            for (int am = 0; am < 4; ++am) {
                int row = a_row_base + am * 16;
                uint32_t off = (uint32_t)row * 128 + ((hb + a_byte) ^ ((row & 7) * 16));
                ldsm4(Ah[am][0], Ah[am][1], Ah[am][2], Ah[am][3], bufA + off);
            }
#pragma unroll
            for (int p = 0; p < 2; ++p) {
                int row = wn * 32 + p * 16 + b_row_off;
                uint32_t off = (uint32_t)row * 128 + ((hb + b_byte) ^ ((row & 7) * 16));
                ldsm4(Bh[p][0], Bh[p][1], Bh[p][2], Bh[p][3], bufB + off);
            }
#pragma unroll
            for (int am = 0; am < 4; ++am)
#pragma unroll
                for (int an = 0; an < 4; ++an)
                    mma16816(c[am][an], Ah[am][0], Ah[am][1], Ah[am][2], Ah[am][3],
                             Bh[an >> 1][(an & 1) * 2], Bh[an >> 1][(an & 1) * 2 + 1]);
            // Al * Bh
#pragma unroll
            for (int am = 0; am < 4; ++am) {
                int row = a_row_base + am * 16;
                uint32_t off = (uint32_t)row * 128 + ((lb + a_byte) ^ ((row & 7) * 16));
                ldsm4(Al[am][0], Al[am][1], Al[am][2], Al[am][3], bufA + off);
            }
#pragma unroll
            for (int am = 0; am < 4; ++am)
#pragma unroll
                for (int an = 0; an < 4; ++an)
                    mma16816(c[am][an], Al[am][0], Al[am][1], Al[am][2], Al[am][3],
                             Bh[an >> 1][(an & 1) * 2], Bh[an >> 1][(an & 1) * 2 + 1]);
            // Ah * Bl
#pragma unroll
            for (int p = 0; p < 2; ++p) {
                int row = wn * 32 + p * 16 + b_row_off;
                uint32_t off = (uint32_t)row * 128 + ((lb + b_byte) ^ ((row & 7) * 16));
                ldsm4(Bl[p][0], Bl[p][1], Bl[p][2], Bl[p][3], bufB + off);
            }
#pragma unroll
            for (int am = 0; am < 4; ++am)
#pragma unroll
                for (int an = 0; an < 4; ++an)
                    mma16816(c[am][an], Ah[am][0], Ah[am][1], Ah[am][2], Ah[am][3],
                             Bl[an >> 1][(an & 1) * 2], Bl[an >> 1][(an & 1) * 2 + 1]);
        }
        stc = (stc == 2) ? 0 : stc + 1;
        stn = (stn == 2) ? 0 : stn + 1;
    }

    // ---- Epilogue ----
    if (MODE == 1) {
#pragma unroll
        for (int am = 0; am < 4; ++am) {
            int r = m0 + wm * 64 + am * 16 + (lane >> 2);
#pragma unroll
            for (int an = 0; an < 4; ++an) {
                int col = n0 + wn * 32 + an * 8 + (lane & 3) * 2;
                float b0 = bias[col], b1 = bias[col + 1];
                float2 v0 = make_float2(c[am][an][0] + b0, c[am][an][1] + b1);
                float2 v1 = make_float2(c[am][an][2] + b0, c[am][an][3] + b1);
                *reinterpret_cast<float2*>(C + (size_t)r * N + col)       = v0;
                *reinterpret_cast<float2*>(C + (size_t)(r + 8) * N + col) = v1;
            }
        }
    } else {
        const int part = n0 >> 11;   // 0=q, 1=k, 2=v
#pragma unroll
        for (int am = 0; am < 4; ++am) {
            int r = m0 + wm * 64 + am * 16 + (lane >> 2);
            int b = r >> 11, s = r & 2047;
#pragma unroll
            for (int an = 0; an < 4; ++an) {
                int n = n0 + wn * 32 + an * 8 + (lane & 3) * 2;
                int h = (n & 2047) >> 7, d = n & 127;
                float v0 = c[am][an][0], v1 = c[am][an][1];
                float v2 = c[am][an][2], v3 = c[am][an][3];
                if (part == 2) {
                    size_t o = (size_t)(b * 2048 + s) * DOUT + h * 128 + d;
                    *reinterpret_cast<float2*>(g_v + o)            = make_float2(v0, v1);
                    *reinterpret_cast<float2*>(g_v + o + 8 * DOUT) = make_float2(v2, v3);
                } else {
                    __nv_bfloat16* dh = (part == 0) ? g_qh : g_kh;
                    __nv_bfloat16* dl = (part == 0) ? g_ql : g_kl;
                    float sc = (part == 0) ? QK_SCALE : 1.0f;
                    size_t o = (size_t)(b * 16 + h) * HEADELEMS + (size_t)s * 128 + d;
                    uint32_t hi, lo;
                    split_pack(v0 * sc, v1 * sc, hi, lo);
                    *reinterpret_cast<uint32_t*>(dh + o) = hi;
                    *reinterpret_cast<uint32_t*>(dl + o) = lo;
                    split_pack(v2 * sc, v3 * sc, hi, lo);
                    *reinterpret_cast<uint32_t*>(dh + o + 8 * 128) = hi;
                    *reinterpret_cast<uint32_t*>(dl + o + 8 * 128) = lo;
                }
            }
        }
    }
}

// ---------------------------------------------------------------------------
// Tensor-core flash attention (bf16x3), causal. Proven: LPT grid +
// last-tile warp skip + Q hoist. Epilogue writes interleaved-packed g_a2.
// ---------------------------------------------------------------------------
#define ATT_SMEM (1024 + 196608)

__global__ __launch_bounds__(256) void k_attn_tc() {
    extern __shared__ char smraw[];
    uint32_t sb = (smem_to_u32(smraw) + 1023) & ~1023u;
    const int tid = threadIdx.x, w = tid >> 5, lane = tid & 31;
    const int qblk = 15 - blockIdx.y;      // global heavy-first (LPT)
    const int bh   = blockIdx.x;
    const int q0   = qblk * 128;
    const size_t hb = (size_t)bh * HEADELEMS;

    const __nv_bfloat16* Qh  = g_qh  + hb + (size_t)q0 * 128;
    const __nv_bfloat16* Ql  = g_ql  + hb + (size_t)q0 * 128;
    const __nv_bfloat16* Kh  = g_kh  + hb;
    const __nv_bfloat16* Kl  = g_kl  + hb;
    const __nv_bfloat16* Vth = g_vth + hb;
    const __nv_bfloat16* Vtl = g_vtl + hb;

    load_rows(sb + 0,     Qh,      128, 128, tid);
    load_rows(sb + 16384, Qh + 64, 128, 128, tid);
    load_rows(sb + 32768, Ql,      128, 128, tid);
    load_rows(sb + 49152, Ql + 64, 128, 128, tid);
    {
        uint32_t kb = sb + 65536, vb = sb + 131072;
        load_rows(kb + 0,     Kh,      128, 64, tid);
        load_rows(kb + 8192,  Kh + 64, 128, 64, tid);
        load_rows(kb + 16384, Kl,      128, 64, tid);
        load_rows(kb + 24576, Kl + 64, 128, 64, tid);
        load_rows(vb + 0,     Vth,     2048, 128, tid);
        load_rows(vb + 16384, Vtl,     2048, 128, tid);
    }
    CP_COMMIT();

    const int ntiles = 2 * qblk + 2;

    float oc[16][4];
#pragma unroll
    for (int i = 0; i < 16; i++)
#pragma unroll
        for (int q = 0; q < 4; q++) oc[i][q] = 0.f;
    float m0 = -1e30f, m1 = -1e30f, l0 = 0.f, l1 = 0.f;

    const int a_row  = w * 16 + ((lane >> 3) & 1) * 8 + (lane & 7);
    const int a_byte = (lane >> 4) * 16;
    const int b_row  = ((lane >> 4) & 1) * 8 + (lane & 7);
    const int b_byte = ((lane >> 3) & 1) * 16;

    uint32_t qfh[8][4], qfl[8][4];

    for (int j = 0; j < ntiles; ++j) {
        if (j + 1 < ntiles) {
            uint32_t kb = sb + 65536  + ((j + 1) & 1) * 32768;
            uint32_t vb = sb + 131072 + ((j + 1) & 1) * 32768;
            const __nv_bfloat16* kh = Kh + (size_t)(j + 1) * 64 * 128;
            const __nv_bfloat16* kl = Kl + (size_t)(j + 1) * 64 * 128;
            load_rows(kb + 0,     kh,      128, 64, tid);
            load_rows(kb + 8192,  kh + 64, 128, 64, tid);
            load_rows(kb + 16384, kl,      128, 64, tid);
            load_rows(kb + 24576, kl + 64, 128, 64, tid);
            load_rows(vb + 0,     Vth + (j + 1) * 64, 2048, 128, tid);
            load_rows(vb + 16384, Vtl + (j + 1) * 64, 2048, 128, tid);
        }
        CP_COMMIT();
        CP_WAIT1();
        __syncthreads();

        if (j == 0) {
#pragma unroll
            for (int kst = 0; kst < 8; ++kst) {
                int ch = kst >> 2, sby = (kst & 3) * 32;
                uint32_t qoff = (uint32_t)a_row * 128 + ((sby + a_byte) ^ ((a_row & 7) * 16));
                ldsm4(qfh[kst][0], qfh[kst][1], qfh[kst][2], qfh[kst][3], sb + ch * 16384 + qoff);
                ldsm4(qfl[kst][0], qfl[kst][1], qfl[kst][2], qfl[kst][3], sb + 32768 + ch * 16384 + qoff);
            }
        }

        if (!(j == ntiles - 1 && w < 4)) {

        uint32_t kb = sb + 65536  + (j & 1) * 32768;
        uint32_t vb = sb + 131072 + (j & 1) * 32768;

        float sc[8][4];
#pragma unroll
        for (int t = 0; t < 8; t++)
#pragma unroll
            for (int q = 0; q < 4; q++) sc[t][q] = 0.f;

#pragma unroll
        for (int kst = 0; kst < 8; ++kst) {
            int ch = kst >> 2, sby = (kst & 3) * 32;
            uint32_t bhf[4][4], blf[4][4];
#pragma unroll
            for (int p = 0; p < 4; ++p) {
                int row = p * 16 + b_row;
                uint32_t off = (uint32_t)row * 128 + ((sby + b_byte) ^ ((row & 7) * 16));
                ldsm4(bhf[p][0], bhf[p][1], bhf[p][2], bhf[p][3], kb + ch * 8192 + off);
                ldsm4(blf[p][0], blf[p][1], blf[p][2], blf[p][3], kb + 16384 + ch * 8192 + off);
            }
#pragma unroll
            for (int t = 0; t < 8; ++t) {
                int p = t >> 1, rr = (t & 1) * 2;
                mma16816(sc[t], qfh[kst][0], qfh[kst][1], qfh[kst][2], qfh[kst][3],
                         bhf[p][rr], bhf[p][rr + 1]);
                mma16816(sc[t], qfh[kst][0], qfh[kst][1], qfh[kst][2], qfh[kst][3],
                         blf[p][rr], blf[p][rr + 1]);
                mma16816(sc[t], qfl[kst][0], qfl[kst][1], qfl[kst][2], qfl[kst][3],
                         bhf[p][rr], bhf[p][rr + 1]);
            }
        }

        if (j >= 2 * qblk) {
            int kbase = j * 64 + (lane & 3) * 2;
            int qrow  = q0 + w * 16 + (lane >> 2);
#pragma unroll
            for (int t = 0; t < 8; ++t) {
                int kc = kbase + t * 8;
                if (kc     > qrow)     sc[t][0] = -1e30f;
                if (kc + 1 > qrow)     sc[t][1] = -1e30f;
                if (kc     > qrow + 8) sc[t][2] = -1e30f;
                if (kc + 1 > qrow + 8) sc[t][3] = -1e30f;
            }
        }

        uint32_t pha0[8], pha1[8], pla0[8], pla1[8];
        float alpha0, alpha1;
        {
            float mx = -1e30f;
#pragma unroll
            for (int t = 0; t < 8; ++t) mx = fmaxf(mx, fmaxf(sc[t][0], sc[t][1]));
            mx = fmaxf(mx, __shfl_xor_sync(0xffffffffu, mx, 1));
            mx = fmaxf(mx, __shfl_xor_sync(0xffffffffu, mx, 2));
            float mn = fmaxf(m0, mx);
            alpha0 = __expf(m0 - mn); m0 = mn;
            float sum = 0.f;
#pragma unroll
            for (int t = 0; t < 8; ++t) {
                float p0 = __expf(sc[t][0] - mn), p1 = __expf(sc[t][1] - mn);
                sum += p0 + p1;
                split_pack(p0, p1, pha0[t], pla0[t]);
            }
            sum += __shfl_xor_sync(0xffffffffu, sum, 1);
            sum += __shfl_xor_sync(0xffffffffu, sum, 2);
            l0 = l0 * alpha0 + sum;
        }
        {
            float mx = -1e30f;
#pragma unroll
            for (int t = 0; t < 8; ++t) mx = fmaxf(mx, fmaxf(sc[t][2], sc[t][3]));
            mx = fmaxf(mx, __shfl_xor_sync(0xffffffffu, mx, 1));
            mx = fmaxf(mx, __shfl_xor_sync(0xffffffffu, mx, 2));
            float mn = fmaxf(m1, mx);
            alpha1 = __expf(m1 - mn); m1 = mn;
            float sum = 0.f;
#pragma unroll
            for (int t = 0; t < 8; ++t) {
                float p0 = __expf(sc[t][2] - mn), p1 = __expf(sc[t][3] - mn);
                sum += p0 + p1;
                split_pack(p0, p1, pha1[t], pla1[t]);
            }
            sum += __shfl_xor_sync(0xffffffffu, sum, 1);
            sum += __shfl_xor_sync(0xffffffffu, sum, 2);
            l1 = l1 * alpha1 + sum;
        }
#pragma unroll
        for (int dt = 0; dt < 16; ++dt) {
            oc[dt][0] *= alpha0; oc[dt][1] *= alpha0;
            oc[dt][2] *= alpha1; oc[dt][3] *= alpha1;
        }

#pragma unroll
        for (int kk = 0; kk < 4; ++kk) {
            uint32_t Ah0 = pha0[2*kk],   Ah1 = pha1[2*kk];
            uint32_t Ah2 = pha0[2*kk+1], Ah3 = pha1[2*kk+1];
            uint32_t Al0 = pla0[2*kk],   Al1 = pla1[2*kk];
            uint32_t Al2 = pla0[2*kk+1], Al3 = pla1[2*kk+1];
            uint32_t bhf[8][4], blf[8][4];
#pragma unroll
            for (int p = 0; p < 8; ++p) {
                int row = p * 16 + b_row;
                uint32_t off = (uint32_t)row * 128 + ((kk * 32 + b_byte) ^ ((row & 7) * 16));
                ldsm4(bhf[p][0], bhf[p][1], bhf[p][2], bhf[p][3], vb + off);
                ldsm4(blf[p][0], blf[p][1], blf[p][2], blf[p][3], vb + 16384 + off);
            }
#pragma unroll
            for (int dt = 0; dt < 16; ++dt) {
                int p = dt >> 1, rr = (dt & 1) * 2;
                mma16816(oc[dt], Ah0, Ah1, Ah2, Ah3, bhf[p][rr], bhf[p][rr + 1]);
                mma16816(oc[dt], Ah0, Ah1, Ah2, Ah3, blf[p][rr], blf[p][rr + 1]);
                mma16816(oc[dt], Al0, Al1, Al2, Al3, bhf[p][rr], bhf[p][rr + 1]);
            }
        }

        }   // end skip guard
        __syncthreads();
    }

    // ---- epilogue: O / l -> g_a2 interleaved packed [hi32|lo32] ----
    float inv0 = 1.f / l0, inv1 = 1.f / l1;
    int b = bh >> 4, h = bh & 15;
    int r0 = q0 + w * 16 + (lane >> 2);
    size_t base0 = (size_t)(b * 2048 + r0) * APACK;
    size_t base1 = base0 + (size_t)8 * APACK;
#pragma unroll
    for (int dt = 0; dt < 16; ++dt) {
        int d = dt * 8 + (lane & 3) * 2;
        uint32_t off = pk(h * 128 + d);
        uint32_t hi, lo;
        split_pack(oc[dt][0] * inv0, oc[dt][1] * inv0, hi, lo);
        *reinterpret_cast<uint32_t*>(g_a2 + base0 + off)      = hi;
        *reinterpret_cast<uint32_t*>(g_a2 + base0 + off + 32) = lo;
        split_pack(oc[dt][2] * inv1, oc[dt][3] * inv1, hi, lo);
        *reinterpret_cast<uint32_t*>(g_a2 + base1 + off)      = hi;
        *reinterpret_cast<uint32_t*>(g_a2 + base1 + off + 32) = lo;
    }
}

// ---------------------------------------------------------------------------
// Launch
// ---------------------------------------------------------------------------
extern "C" void kernel_launch(void* const* d_in, const int* in_sizes, int n_in,
                              void* d_out, int out_size) {
    const float* x     = (const float*)d_in[0];
    const float* Wqkv  = (const float*)d_in[1];
    const float* Wproj = (const float*)d_in[2];
    const float* bproj = (const float*)d_in[3];
    float* out = (float*)d_out;
    (void)in_sizes; (void)n_in; (void)out_size;

    cudaFuncSetAttribute(k_gemm_v7<0>, cudaFuncAttributeMaxDynamicSharedMemorySize, GEMM_SMEM);
    cudaFuncSetAttribute(k_gemm_v7<1>, cudaFuncAttributeMaxDynamicSharedMemorySize, GEMM_SMEM);
    cudaFuncSetAttribute(k_attn_tc,    cudaFuncAttributeMaxDynamicSharedMemorySize, ATT_SMEM);

    __nv_bfloat16 *x2, *wq2, *wp2, *a2;
    cudaGetSymbolAddress((void**)&x2,  g_x2);
    cudaGetSymbolAddress((void**)&wq2, g_wq2);
    cudaGetSymbolAddress((void**)&wp2, g_wp2);
    cudaGetSymbolAddress((void**)&a2,  g_a2);

    // 1) Pack inputs (interleaved hi|lo)
    k_split_pack<<<(ROWS * 2048 / 4) / 256, 256>>>(x, x2);
    k_tsplit_pack<<<dim3(QKVCOLS / 32, 2048 / 32), dim3(32, 8)>>>(Wqkv, wq2, QKVCOLS);
    k_tsplit_pack<<<dim3(DOUT / 32, 2048 / 32), dim3(32, 8)>>>(Wproj, wp2, DOUT);

    // 2) GEMM1 fused: q/k hi-lo splits (scaled) + fp32 V
    k_gemm_v7<0><<<dim3(QKVCOLS / 128, ROWS / 128), 256, GEMM_SMEM>>>(
        x2, wq2, nullptr, nullptr, QKVCOLS);

    // 3) V transpose+split
    k_prep_vt<<<dim3(4, 64, 32), dim3(32, 8)>>>();

    // 4) Tensor-core attention -> g_a2 (LPT grid)
    k_attn_tc<<<dim3(32, 16), 256, ATT_SMEM>>>();

    // 5) GEMM2: out = attn @ Wproj + bias
    k_gemm_v7<1><<<dim3(DOUT / 128, ROWS / 128), 256, GEMM_SMEM>>>(
        a2, wp2, bproj, out, DOUT);
}